// round 3
// baseline (speedup 1.0000x reference)
#include <cuda_runtime.h>
#include <cstdint>

// Problem constants
#define B_DIM   16
#define L_DIM   160000
#define N_WT    10
#define WT_LEN  512
#define FIR_TAPS 31
#define WT_TOT  (N_WT * WT_LEN)

// Blocked-scan parameters (XLA ReduceWindowRewriter, base_length = 16)
// levels: 160000 -> 10000 -> 625 (pad 640) -> 40 (pad 48) -> 3 (sequential)
#define NS1 10000
#define NS2 625
#define NS3 40
#define NS4 3

// K = (512 / 16000) rounded to f32
__device__ __forceinline__ float KF() { return (float)(512.0 / 16000.0); }

// Scratch
__device__ float g_S1[B_DIM][NS1];   // 16-block sums of increments
__device__ float g_O1[B_DIM][NS1];   // inclusive scan of S1 (composed)
__device__ float g_wt[WT_TOT];       // FIR-filtered wavetables

// ---------------------------------------------------------------------------
// FIR: circular-pad + cross-correlate each wavetable with fir_h (strict rn,
// sequential ascending taps, no FMA contraction)
// ---------------------------------------------------------------------------
__global__ void k_fir(const float* __restrict__ wtab, const float* __restrict__ h)
{
    __shared__ float sh[FIR_TAPS];
    if (threadIdx.x < FIR_TAPS) sh[threadIdx.x] = h[threadIdx.x];
    __syncthreads();
    for (int idx = threadIdx.x; idx < WT_TOT; idx += blockDim.x) {
        int w = idx >> 9;
        int i = idx & 511;
        const float* row = wtab + w * WT_LEN;
        float s = 0.0f;
        #pragma unroll
        for (int k = 0; k < FIR_TAPS; k++) {
            int j = (i + k - 15 + WT_LEN) & 511;
            s = __fadd_rn(s, __fmul_rn(row[j], sh[k]));
        }
        g_wt[idx] = s;
    }
}

// ---------------------------------------------------------------------------
// S1[j] = sequential sum of 16 increments x[16j..16j+15], x = rn(k * pitch).
// Strict left-to-right rn adds starting from 0 (0+x exact).
// ---------------------------------------------------------------------------
__global__ void k_s1(const float* __restrict__ pitch)
{
    const int j = blockIdx.x * 256 + threadIdx.x;
    const int b = blockIdx.y;
    if (j >= NS1) return;
    const float k = KF();
    const float* P = pitch + b * L_DIM + (j << 4);
    float acc = 0.0f;
    #pragma unroll
    for (int e = 0; e < 16; e++)
        acc = __fadd_rn(acc, __fmul_rn(k, P[e]));
    g_S1[b][j] = acc;
}

// ---------------------------------------------------------------------------
// Per-row hierarchical scan composition (one block per batch row):
//   S2[625] <- 16-block seq sums of S1
//   S3[40]  <- 16-block seq sums of S2 (padded with zeros: exact no-ops)
//   S4[3]   <- 16-block seq sums of S3 (padded)
//   O4      <- sequential scan of S4
//   O3[m]   = innerseq(S3 block) (+ O4[blk-1] if blk>0)
//   O2[m]   = innerseq(S2 block) (+ O3[blk-1] if blk>0)
//   O1[m]   = innerseq(S1 block) (+ O2[blk-1] if blk>0)   -> global
// ---------------------------------------------------------------------------
__global__ void k_scan()
{
    __shared__ float sS1[NS1];
    __shared__ float sS2[NS2];
    __shared__ float sS3[NS3];
    __shared__ float sS4[NS4];
    __shared__ float sO4[NS4];
    __shared__ float sO3[NS3];
    __shared__ float sO2[NS2];

    const int b   = blockIdx.x;
    const int tid = threadIdx.x;

    for (int m = tid; m < NS1; m += blockDim.x) sS1[m] = g_S1[b][m];
    __syncthreads();

    // S2
    for (int j = tid; j < NS2; j += blockDim.x) {
        float acc = 0.0f;
        #pragma unroll
        for (int e = 0; e < 16; e++)
            acc = __fadd_rn(acc, sS1[(j << 4) + e]);
        sS2[j] = acc;
    }
    __syncthreads();

    // S3 (625 padded to 640: indices >= 625 are zeros -> skip, add(acc,0) exact)
    if (tid < NS3) {
        float acc = 0.0f;
        for (int e = 0; e < 16; e++) {
            int idx = (tid << 4) + e;
            if (idx < NS2) acc = __fadd_rn(acc, sS2[idx]);
        }
        sS3[tid] = acc;
    }
    __syncthreads();

    // S4 (40 padded to 48)
    if (tid < NS4) {
        float acc = 0.0f;
        for (int e = 0; e < 16; e++) {
            int idx = (tid << 4) + e;
            if (idx < NS3) acc = __fadd_rn(acc, sS3[idx]);
        }
        sS4[tid] = acc;
    }
    __syncthreads();

    // O4: sequential scan of 3 elements
    if (tid == 0) {
        float acc = 0.0f;
        for (int m = 0; m < NS4; m++) {
            acc = __fadd_rn(acc, sS4[m]);
            sO4[m] = acc;
        }
    }
    __syncthreads();

    // O3
    if (tid < NS3) {
        int blk = tid >> 4;
        float acc = 0.0f;
        for (int m = (blk << 4); m <= tid; m++)
            acc = __fadd_rn(acc, sS3[m]);
        sO3[tid] = blk ? __fadd_rn(acc, sO4[blk - 1]) : acc;
    }
    __syncthreads();

    // O2
    if (tid < NS2) {
        int blk = tid >> 4;
        float acc = 0.0f;
        for (int m = (blk << 4); m <= tid; m++)
            acc = __fadd_rn(acc, sS2[m]);
        sO2[tid] = blk ? __fadd_rn(acc, sO3[blk - 1]) : acc;
    }
    __syncthreads();

    // O1: thread per 16-block of S1, running inner scan + compose
    for (int j = tid; j < NS2; j += blockDim.x) {
        float prev = (j > 0) ? sO2[j - 1] : 0.0f;
        float acc = 0.0f;
        #pragma unroll
        for (int r = 0; r < 16; r++) {
            int m = (j << 4) + r;
            acc = __fadd_rn(acc, sS1[m]);
            g_O1[b][m] = (j > 0) ? __fadd_rn(acc, prev) : acc;
        }
    }
}

// ---------------------------------------------------------------------------
// Main: cumsum[b][t] = innerseq(x block up to t) (+ O1[t/16 - 1]), then
// index = cumsum - rn(k*pitch_row0[t]), remainder/snap/interp/dot/envelope,
// all strict-rn non-contracted.
// ---------------------------------------------------------------------------
__global__ void k_main(const float* __restrict__ pitch,
                       const float* __restrict__ env,
                       const float* __restrict__ att,
                       float* __restrict__ out)
{
    __shared__ float swt[WT_TOT];
    const int tid = threadIdx.x;
    for (int i = tid; i < WT_TOT; i += 256) swt[i] = g_wt[i];
    __syncthreads();

    const int t = blockIdx.x * 256 + tid;   // 625 * 256 == 160000
    const int b = blockIdx.y;
    const float k = KF();

    const int j0 = t >> 4;
    const int r0 = t & 15;
    const float* PB = pitch + b * L_DIM + (j0 << 4);

    float acc = 0.0f;
    for (int e = 0; e <= r0; e++)
        acc = __fadd_rn(acc, __fmul_rn(k, PB[e]));
    float v = j0 ? __fadd_rn(acc, g_O1[b][j0 - 1]) : acc;

    // index = cumsum - increment_row0[t] (materialized mul, plain subtract)
    float index = __fsub_rn(v, __fmul_rn(k, pitch[t]));

    // jnp.remainder(index, 512)
    float r = fmodf(index, 512.0f);
    if (r < 0.0f) r = __fadd_rn(r, 512.0f);
    if (__fsub_rn(512.0f, r) < 1e-5f) r = 0.0f;

    float lof   = floorf(r);
    float alpha = __fsub_rn(r, lof);
    int   ilo   = (int)lof;
    int   ihi   = ((int)ceilf(r)) & 511;   // 512 -> 0, else identity

    const int base = b * L_DIM + t;
    const float* ap = att + (size_t)base * N_WT;
    float acc2 = 0.0f;
    #pragma unroll
    for (int w = 0; w < N_WT; w++) {
        float lo = swt[w * WT_LEN + ilo];
        float hi = swt[w * WT_LEN + ihi];
        float wave = __fadd_rn(lo, __fmul_rn(alpha, __fsub_rn(hi, lo)));
        acc2 = __fadd_rn(acc2, __fmul_rn(wave, ap[w]));
    }
    out[base] = __fmul_rn(acc2, env[base]);
}

// ---------------------------------------------------------------------------
// d_in order: 0 pitch, 1 envelope, 2 attention, 3 wavetables, 4 fir_h
// ---------------------------------------------------------------------------
extern "C" void kernel_launch(void* const* d_in, const int* in_sizes, int n_in,
                              void* d_out, int out_size)
{
    const float* pitch = (const float*)d_in[0];
    const float* env   = (const float*)d_in[1];
    const float* att   = (const float*)d_in[2];
    const float* wtab  = (const float*)d_in[3];
    const float* firh  = (const float*)d_in[4];
    float* out = (float*)d_out;

    k_fir<<<1, 512>>>(wtab, firh);
    k_s1<<<dim3(40, B_DIM), 256>>>(pitch);
    k_scan<<<B_DIM, 1024>>>();
    k_main<<<dim3(625, B_DIM), 256>>>(pitch, env, att, out);
}

// round 4
// speedup vs baseline: 1.2159x; 1.2159x over previous
#include <cuda_runtime.h>
#include <cstdint>

// Problem constants
#define B_DIM   16
#define L_DIM   160000
#define N_WT    10
#define WT_LEN  512
#define FIR_TAPS 31
#define WT_TOT  (N_WT * WT_LEN)

// Blocked-scan parameters (XLA ReduceWindowRewriter, base_length = 16)
#define NS1 10000
#define NS2 625
#define NS3 40
#define NS4 3

#define TPB 640            // k_main threads per block (160000 / 640 = 250)

__device__ __forceinline__ float KF() { return (float)(512.0 / 16000.0); }

// Scratch
__device__ float g_S1[B_DIM][NS1];   // 16-block sums of increments
__device__ float g_O1[B_DIM][NS1];   // inclusive scan of S1 (composed)
__device__ float g_wt[WT_TOT];       // FIR-filtered wavetables

// ---------------------------------------------------------------------------
// FIR: circular-pad + cross-correlate each wavetable with fir_h (strict rn)
// ---------------------------------------------------------------------------
__global__ void k_fir(const float* __restrict__ wtab, const float* __restrict__ h)
{
    __shared__ float sh[FIR_TAPS];
    if (threadIdx.x < FIR_TAPS) sh[threadIdx.x] = h[threadIdx.x];
    __syncthreads();
    for (int idx = threadIdx.x; idx < WT_TOT; idx += blockDim.x) {
        int w = idx >> 9;
        int i = idx & 511;
        const float* row = wtab + w * WT_LEN;
        float s = 0.0f;
        #pragma unroll
        for (int k = 0; k < FIR_TAPS; k++) {
            int j = (i + k - 15 + WT_LEN) & 511;
            s = __fadd_rn(s, __fmul_rn(row[j], sh[k]));
        }
        g_wt[idx] = s;
    }
}

// ---------------------------------------------------------------------------
// S1[j] = strict sequential sum of 16 increments rn(k * pitch)
// ---------------------------------------------------------------------------
__global__ void k_s1(const float* __restrict__ pitch)
{
    const int j = blockIdx.x * 256 + threadIdx.x;
    const int b = blockIdx.y;
    if (j >= NS1) return;
    const float k = KF();
    const float* P = pitch + b * L_DIM + (j << 4);
    float acc = 0.0f;
    #pragma unroll
    for (int e = 0; e < 16; e++)
        acc = __fadd_rn(acc, __fmul_rn(k, P[e]));
    g_S1[b][j] = acc;
}

// ---------------------------------------------------------------------------
// Per-row hierarchical scan composition (one block per batch row).
// ---------------------------------------------------------------------------
__global__ void k_scan()
{
    __shared__ float sS1[NS1];
    __shared__ float sS2[NS2];
    __shared__ float sS3[NS3];
    __shared__ float sS4[NS4];
    __shared__ float sO4[NS4];
    __shared__ float sO3[NS3];
    __shared__ float sO2[NS2];

    const int b   = blockIdx.x;
    const int tid = threadIdx.x;

    for (int m = tid; m < NS1; m += blockDim.x) sS1[m] = g_S1[b][m];
    __syncthreads();

    for (int j = tid; j < NS2; j += blockDim.x) {
        float acc = 0.0f;
        #pragma unroll
        for (int e = 0; e < 16; e++)
            acc = __fadd_rn(acc, sS1[(j << 4) + e]);
        sS2[j] = acc;
    }
    __syncthreads();

    if (tid < NS3) {
        float acc = 0.0f;
        for (int e = 0; e < 16; e++) {
            int idx = (tid << 4) + e;
            if (idx < NS2) acc = __fadd_rn(acc, sS2[idx]);
        }
        sS3[tid] = acc;
    }
    __syncthreads();

    if (tid < NS4) {
        float acc = 0.0f;
        for (int e = 0; e < 16; e++) {
            int idx = (tid << 4) + e;
            if (idx < NS3) acc = __fadd_rn(acc, sS3[idx]);
        }
        sS4[tid] = acc;
    }
    __syncthreads();

    if (tid == 0) {
        float acc = 0.0f;
        for (int m = 0; m < NS4; m++) {
            acc = __fadd_rn(acc, sS4[m]);
            sO4[m] = acc;
        }
    }
    __syncthreads();

    if (tid < NS3) {
        int blk = tid >> 4;
        float acc = 0.0f;
        for (int m = (blk << 4); m <= tid; m++)
            acc = __fadd_rn(acc, sS3[m]);
        sO3[tid] = blk ? __fadd_rn(acc, sO4[blk - 1]) : acc;
    }
    __syncthreads();

    if (tid < NS2) {
        int blk = tid >> 4;
        float acc = 0.0f;
        for (int m = (blk << 4); m <= tid; m++)
            acc = __fadd_rn(acc, sS2[m]);
        sO2[tid] = blk ? __fadd_rn(acc, sO3[blk - 1]) : acc;
    }
    __syncthreads();

    for (int j = tid; j < NS2; j += blockDim.x) {
        float prev = (j > 0) ? sO2[j - 1] : 0.0f;
        float acc = 0.0f;
        #pragma unroll
        for (int r = 0; r < 16; r++) {
            int m = (j << 4) + r;
            acc = __fadd_rn(acc, sS1[m]);
            g_O1[b][m] = (j > 0) ? __fadd_rn(acc, prev) : acc;
        }
    }
}

// ---------------------------------------------------------------------------
// Main. Per block: pair wavetable (lo,next) in smem + staged increments.
//  - attention via float2 loads (8B-aligned always)
//  - remainder via exact fma(-512, trunc(x/512), x)  (== fmodf bitwise)
//  - wavetable lo/hi from one LDS.64 (alpha==0 case bitwise-safe)
// ---------------------------------------------------------------------------
__global__ void __launch_bounds__(TPB) k_main(
        const float* __restrict__ pitch,
        const float* __restrict__ env,
        const float* __restrict__ att,
        float* __restrict__ out)
{
    __shared__ float2 sp[WT_TOT];     // 40 KB pair table
    __shared__ float  sinc[TPB];      // staged increments

    const int tid = threadIdx.x;
    const int b   = blockIdx.y;
    const int t   = blockIdx.x * TPB + tid;   // 250 * 640 == 160000
    const float k = KF();

    // build (value, next-value) pair table; both reads coalesced
    for (int i = tid; i < WT_TOT; i += TPB) {
        int base_w = i & ~511;
        int j = i & 511;
        float lo = g_wt[i];
        float hi = g_wt[base_w | ((j + 1) & 511)];
        sp[i] = make_float2(lo, hi);
    }

    // stage this tile's increments (blocks of 16 never straddle tiles: 640 % 16 == 0)
    sinc[tid] = __fmul_rn(k, pitch[b * L_DIM + t]);
    __syncthreads();

    // strict sequential prefix within the 16-block, from staged increments
    const int r0 = tid & 15;
    const int lb = tid & ~15;
    float acc = 0.0f;
    for (int e = 0; e <= r0; e++)
        acc = __fadd_rn(acc, sinc[lb + e]);
    const int j0 = t >> 4;
    float v = j0 ? __fadd_rn(acc, g_O1[b][j0 - 1]) : acc;

    // index = cumsum - rn(k * pitch_row0[t])
    float index = __fsub_rn(v, __fmul_rn(k, pitch[t]));

    // exact trunc-remainder by 512 (bitwise == fmodf), then jnp.remainder fixup
    float q = truncf(__fmul_rn(index, 0.001953125f));   // x/512 exact
    float r = __fmaf_rn(-512.0f, q, index);             // exact residual
    if (r < 0.0f) r = __fadd_rn(r, 512.0f);
    if (__fsub_rn(512.0f, r) < 1e-5f) r = 0.0f;

    float lof   = floorf(r);
    float alpha = __fsub_rn(r, lof);
    int   ilo   = (int)lof;

    const int base = b * L_DIM + t;
    const float2* ap = (const float2*)(att + (size_t)base * N_WT);
    float2 a0 = ap[0], a1 = ap[1], a2 = ap[2], a3 = ap[3], a4 = ap[4];
    float aw[N_WT] = {a0.x, a0.y, a1.x, a1.y, a2.x, a2.y, a3.x, a3.y, a4.x, a4.y};

    float acc2 = 0.0f;
    #pragma unroll
    for (int w = 0; w < N_WT; w++) {
        float2 pr = sp[w * WT_LEN + ilo];
        float wave = __fadd_rn(pr.x, __fmul_rn(alpha, __fsub_rn(pr.y, pr.x)));
        acc2 = __fadd_rn(acc2, __fmul_rn(wave, aw[w]));
    }
    out[base] = __fmul_rn(acc2, env[base]);
}

// ---------------------------------------------------------------------------
// d_in order: 0 pitch, 1 envelope, 2 attention, 3 wavetables, 4 fir_h
// ---------------------------------------------------------------------------
extern "C" void kernel_launch(void* const* d_in, const int* in_sizes, int n_in,
                              void* d_out, int out_size)
{
    const float* pitch = (const float*)d_in[0];
    const float* env   = (const float*)d_in[1];
    const float* att   = (const float*)d_in[2];
    const float* wtab  = (const float*)d_in[3];
    const float* firh  = (const float*)d_in[4];
    float* out = (float*)d_out;

    k_fir<<<1, 512>>>(wtab, firh);
    k_s1<<<dim3(40, B_DIM), 256>>>(pitch);
    k_scan<<<B_DIM, 1024>>>();
    k_main<<<dim3(250, B_DIM), TPB>>>(pitch, env, att, out);
}